// round 9
// baseline (speedup 1.0000x reference)
#include <cuda_runtime.h>
#include <cuda_bf16.h>

// LeakyAvg: out[b,h,t,d] = sum_{s<=t} exp(-beta_h*(t-s)) * k[b,h,s,d]
// = recurrence y[t] = w*y[t-1] + k[t], w = exp(-beta_h), beta_h in [0.5, 5].
//
// R9: R8's barrier-free pipelined scan, widened to a 128-bit datapath.
//  - Lane owns 4 head-dims (float4). HS=64 -> 16 lanes per timestep, so a
//    warp services TWO (b,h) rows: lanes 0-15 -> row 2q, lanes 16-31 ->
//    row 2q+1. Each half-warp's access is 256B contiguous => LDG.128/STG.128,
//    half the memory instructions / L1 wavefronts of the float2 version.
//  - w differs per half-warp (different h) -> per-lane register, free.
//  - BODY=32 (+WARM=24 halo, truncation e^{-12}~6e-6, validated R5-R8).
//    Pipeline: groups of 4 timesteps, double-buffered (buf[2][4] float4),
//    next group's loads issue before current group's scan -> 2KB always in
//    flight per warp. 2048 warps = one wave, no barriers.

#define BB 4
#define NH 16
#define TT 2048
#define HS 64
#define EXP_SCALING 10.0f

#define BODY 32                  // stored timesteps per warp
#define WARMS 24                 // warm-up halo
#define G 4                      // pipeline group size (timesteps)
#define NG ((BODY + WARMS) / G)  // 14 groups
#define WARMG (WARMS / G)        // 6 warm groups

#define NTILES (TT / BODY)       // 64
#define NPAIRS (BB * NH / 2)     // 32 row-pairs
#define NWARPS (NPAIRS * NTILES) // 2048
#define TPB 128
#define NBLK (NWARPS * 32 / TPB) // 512

#define F4_PER_T (HS / 4)        // 16 float4 per timestep-row

__global__ void __launch_bounds__(TPB) leaky_avg_kernel(
    const float* __restrict__ k,
    const float* __restrict__ beta_param,
    float* __restrict__ out)
{
    const int gw   = (blockIdx.x * TPB + threadIdx.x) >> 5;  // global warp
    const int lane = threadIdx.x & 31;
    const int tile = gw & (NTILES - 1);          // 0..63
    const int pair = gw >> 6;                    // 0..31
    const int sub  = lane >> 4;                  // 0: row 2q, 1: row 2q+1
    const int dg   = lane & 15;                  // float4 group within HS
    const int row  = 2 * pair + sub;
    const int h    = row & (NH - 1);

    const float w = expf(-fabsf(beta_param[h]) * EXP_SCALING);

    const int t0     = tile * BODY;
    const int startT = t0 - WARMS;   // negative only for tile 0 warm groups

    const float4* __restrict__ kp =
        reinterpret_cast<const float4*>(k) + (size_t)row * TT * F4_PER_T + dg;
    float4* __restrict__ op =
        reinterpret_cast<float4*>(out) + (size_t)row * TT * F4_PER_T + dg;

    float4 buf[2][G];

    // prologue: load group 0 (tile 0's warm groups: uniform zero-fill)
    {
        const int tg = startT;
        if (tg >= 0) {
            #pragma unroll
            for (int u = 0; u < G; ++u)
                buf[0][u] = kp[(size_t)(tg + u) * F4_PER_T];
        } else {
            #pragma unroll
            for (int u = 0; u < G; ++u)
                buf[0][u] = make_float4(0.0f, 0.0f, 0.0f, 0.0f);
        }
    }

    float4 y = make_float4(0.0f, 0.0f, 0.0f, 0.0f);

    #pragma unroll
    for (int g = 0; g < NG; ++g) {
        // issue next group's loads before consuming current buffer
        if (g + 1 < NG) {
            const int tg = startT + (g + 1) * G;
            if (tg >= 0) {
                #pragma unroll
                for (int u = 0; u < G; ++u)
                    buf[(g + 1) & 1][u] = kp[(size_t)(tg + u) * F4_PER_T];
            } else {
                #pragma unroll
                for (int u = 0; u < G; ++u)
                    buf[(g + 1) & 1][u] = make_float4(0.0f, 0.0f, 0.0f, 0.0f);
            }
        }

        const float4* b = buf[g & 1];
        if (g < WARMG) {
            #pragma unroll
            for (int u = 0; u < G; ++u) {
                y.x = fmaf(w, y.x, b[u].x);
                y.y = fmaf(w, y.y, b[u].y);
                y.z = fmaf(w, y.z, b[u].z);
                y.w = fmaf(w, y.w, b[u].w);
            }
        } else {
            const int tg = startT + g * G;   // >= t0 here
            #pragma unroll
            for (int u = 0; u < G; ++u) {
                y.x = fmaf(w, y.x, b[u].x);
                y.y = fmaf(w, y.y, b[u].y);
                y.z = fmaf(w, y.z, b[u].z);
                y.w = fmaf(w, y.w, b[u].w);
                __stcs(op + (size_t)(tg + u) * F4_PER_T, y);
            }
        }
    }
}

extern "C" void kernel_launch(void* const* d_in, const int* in_sizes, int n_in,
                              void* d_out, int out_size)
{
    const float* k    = (const float*)d_in[0];   // (B, NH, T, HS) f32
    const float* beta = (const float*)d_in[1];   // (1, NH, 1, 1) f32
    float*       out  = (float*)d_out;           // (B, NH, T, HS) f32

    leaky_avg_kernel<<<NBLK, TPB>>>(k, beta, out);
}

// round 10
// speedup vs baseline: 1.0573x; 1.0573x over previous
#include <cuda_runtime.h>
#include <cuda_bf16.h>

// LeakyAvg: out[b,h,t,d] = sum_{s<=t} exp(-beta_h*(t-s)) * k[b,h,s,d]
// = recurrence y[t] = w*y[t-1] + k[t], w = exp(-beta_h), beta_h in [0.5, 5].
//
// R10 = R8 (best: 11.87us) with ONE change: plain write-back stores instead
// of __stcs evict-first. Input (33.5MB) + output (33.5MB) both fit in L2
// (~126MB); under graph replay the same buffers recur every iteration, so
// normal caching lets reads hit L2-resident input and writes hit resident
// output lines -> steady-state DRAM traffic collapses. __stcs was forcing a
// full 33.5MB DRAM write stream every replay.
//
// Structure (validated R8): warp owns BODY=32 timesteps + WARM=24 halo
// (truncation e^{-12} ~ 6e-6 rel), lane owns 2 head-dims (float2, 256B
// coalesced), 7 groups of 8 double-buffered so 8 loads are always in flight,
// no barriers; 4096 warps = one resident wave.

#define BB 4
#define NH 16
#define TT 2048
#define HS 64
#define EXP_SCALING 10.0f

#define BODY 32                 // stored timesteps per warp
#define WARMS 24                // warm-up halo
#define G 8                     // group (pipeline stage) size
#define NG ((BODY + WARMS) / G) // 7 groups
#define WARMG (WARMS / G)       // 3 warm groups

#define NTILES (TT / BODY)      // 64
#define NROWS (BB * NH)         // 64
#define NWARPS (NROWS * NTILES) // 4096
#define TPB 64                  // 2 warps per block
#define NBLK (NWARPS * 32 / TPB)

__global__ void __launch_bounds__(TPB) leaky_avg_kernel(
    const float* __restrict__ k,
    const float* __restrict__ beta_param,
    float* __restrict__ out)
{
    const int gw   = (blockIdx.x * TPB + threadIdx.x) >> 5;  // global warp
    const int lane = threadIdx.x & 31;
    const int tile = gw & (NTILES - 1);
    const int row  = gw >> 6;                                // / NTILES
    const int h    = row & (NH - 1);

    const float w = expf(-fabsf(beta_param[h]) * EXP_SCALING);

    const int t0     = tile * BODY;
    const int startT = t0 - WARMS;     // negative only for tile 0 (groups 0..2)

    const float2* __restrict__ kp =
        reinterpret_cast<const float2*>(k + (size_t)row * TT * HS) + lane;
    float2* __restrict__ op =
        reinterpret_cast<float2*>(out + (size_t)row * TT * HS) + lane;

    float2 buf[2][G];

    // prologue: load group 0
    {
        const int tg = startT;
        if (tg >= 0) {
            #pragma unroll
            for (int u = 0; u < G; ++u)
                buf[0][u] = kp[(size_t)(tg + u) * (HS / 2)];
        } else {
            #pragma unroll
            for (int u = 0; u < G; ++u)
                buf[0][u] = make_float2(0.0f, 0.0f);
        }
    }

    float2 y = make_float2(0.0f, 0.0f);

    #pragma unroll
    for (int g = 0; g < NG; ++g) {
        // issue next group's loads before touching current buffer
        if (g + 1 < NG) {
            const int tg = startT + (g + 1) * G;
            if (tg >= 0) {
                #pragma unroll
                for (int u = 0; u < G; ++u)
                    buf[(g + 1) & 1][u] = kp[(size_t)(tg + u) * (HS / 2)];
            } else {
                #pragma unroll
                for (int u = 0; u < G; ++u)
                    buf[(g + 1) & 1][u] = make_float2(0.0f, 0.0f);
            }
        }

        const float2* b = buf[g & 1];
        if (g < WARMG) {
            // warm-up: scan only
            #pragma unroll
            for (int u = 0; u < G; ++u) {
                y.x = fmaf(w, y.x, b[u].x);
                y.y = fmaf(w, y.y, b[u].y);
            }
        } else {
            // body: scan + store (tg = t0 + (g-WARMG)*G >= 0 always)
            const int tg = startT + g * G;
            #pragma unroll
            for (int u = 0; u < G; ++u) {
                y.x = fmaf(w, y.x, b[u].x);
                y.y = fmaf(w, y.y, b[u].y);
                float2 r; r.x = y.x; r.y = y.y;
                op[(size_t)(tg + u) * (HS / 2)] = r;   // plain write-back store
            }
        }
    }
}

extern "C" void kernel_launch(void* const* d_in, const int* in_sizes, int n_in,
                              void* d_out, int out_size)
{
    const float* k    = (const float*)d_in[0];   // (B, NH, T, HS) f32
    const float* beta = (const float*)d_in[1];   // (1, NH, 1, 1) f32
    float*       out  = (float*)d_out;           // (B, NH, T, HS) f32

    leaky_avg_kernel<<<NBLK, TPB>>>(k, beta, out);
}